// round 7
// baseline (speedup 1.0000x reference)
#include <cuda_runtime.h>
#include <cuda_bf16.h>
#include <math.h>
#include <stdint.h>

// TopKRouter: x[4,4096,4096] fp32, gate_w[64,4096] fp32
// logits = x @ w^T [16384,64]; softmax; top-2; z_loss = mean(logits^2)
// out fp32: [0,32768) idx | [32768,65536) scores | [65536] aux=0 | [65537] z_loss
//
// sm_103 BASE target (no tcgen05!). GEMM via mma.sync bf16 hi/lo split (3 passes)
// + exact fp32 fixup for tokens with ambiguous top-k gaps.

#define M_TOT 16384
#define H_DIM 4096
#define E_NUM 64
#define MT    128
#define KC    64
#define NC    (H_DIM / KC)     // 64
#define NBLK  (M_TOT / MT)     // 128
#define GAP_TH 2e-3f

// per-stage smem byte offsets
#define AH_O 0
#define AL_O 16384
#define BH_O 32768
#define BL_O 40960
#define STG  49152
#define DSMB (2 * STG + 128)   // 98432

__device__ float g_partials[NBLK];
__device__ unsigned char g_flags[M_TOT];

__device__ __forceinline__ uint32_t smem_u32(const void* p) {
    uint32_t a;
    asm("{ .reg .u64 t; cvta.to.shared.u64 t, %1; cvt.u32.u64 %0, t; }" : "=r"(a) : "l"(p));
    return a;
}

#define LDM4(r, a) \
    asm volatile("ldmatrix.sync.aligned.m8n8.x4.shared.b16 {%0,%1,%2,%3}, [%4];" \
        : "=r"((r)[0]), "=r"((r)[1]), "=r"((r)[2]), "=r"((r)[3]) : "r"(a))

#define MMA(c, a, b0, b1) \
    asm volatile("mma.sync.aligned.m16n8k16.row.col.f32.bf16.bf16.f32 " \
        "{%0,%1,%2,%3},{%4,%5,%6,%7},{%8,%9},{%0,%1,%2,%3};" \
        : "+f"((c)[0]), "+f"((c)[1]), "+f"((c)[2]), "+f"((c)[3]) \
        : "r"((a)[0]), "r"((a)[1]), "r"((a)[2]), "r"((a)[3]), "r"(b0), "r"(b1))

// split float4 into bf16 hi/lo quads, store 8B each (SW128 swizzle)
__device__ __forceinline__ void cvtst(float4 v, uint32_t hi, uint32_t lo, int row, int q) {
    uint32_t off = (uint32_t)row * 128u + (((uint32_t)q * 8u) ^ (((uint32_t)row & 7u) << 4));
    uint32_t h01, h23, l01, l23;
    asm("cvt.rn.bf16x2.f32 %0, %1, %2;" : "=r"(h01) : "f"(v.y), "f"(v.x));
    asm("cvt.rn.bf16x2.f32 %0, %1, %2;" : "=r"(h23) : "f"(v.w), "f"(v.z));
    float hx = __uint_as_float(h01 << 16), hy = __uint_as_float(h01 & 0xffff0000u);
    float hz = __uint_as_float(h23 << 16), hw = __uint_as_float(h23 & 0xffff0000u);
    asm("cvt.rn.bf16x2.f32 %0, %1, %2;" : "=r"(l01) : "f"(v.y - hy), "f"(v.x - hx));
    asm("cvt.rn.bf16x2.f32 %0, %1, %2;" : "=r"(l23) : "f"(v.w - hw), "f"(v.z - hz));
    asm volatile("st.shared.v2.u32 [%0], {%1,%2};" :: "r"(hi + off), "r"(h01), "r"(h23) : "memory");
    asm volatile("st.shared.v2.u32 [%0], {%1,%2};" :: "r"(lo + off), "r"(l01), "r"(l23) : "memory");
}

__device__ __forceinline__ void load_chunk(
    const float* __restrict__ x, const float* __restrict__ w,
    int m0, int k0, int tid, float4 (&ra)[8], float4 (&rb)[4])
{
#pragma unroll
    for (int j = 0; j < 8; j++) {
        int s = tid + j * 256, row = s >> 4, q = s & 15;
        ra[j] = *(const float4*)&x[(size_t)(m0 + row) * H_DIM + k0 + q * 4];
    }
#pragma unroll
    for (int j = 0; j < 4; j++) {
        int s = tid + j * 256, row = s >> 4, q = s & 15;
        rb[j] = *(const float4*)&w[(size_t)row * H_DIM + k0 + q * 4];
    }
}

extern __shared__ char dsm_raw[];

__global__ __launch_bounds__(256, 1)
void router_main(const float* __restrict__ x, const float* __restrict__ w,
                 float* __restrict__ out)
{
    __shared__ float zsh[8];

    const int tid = threadIdx.x;
    const int wid = tid >> 5, lid = tid & 31;
    const int wm = wid & 3, wn = wid >> 2;     // warp tile: rows wm*32, experts wn*32
    const int m0 = blockIdx.x * MT;

    uint32_t raw   = smem_u32(dsm_raw);
    uint32_t sbase = (raw + 127u) & ~127u;

    // per-lane ldmatrix address constants
    const uint32_t sxor  = ((uint32_t)(lid & 7)) << 4;
    const uint32_t aoff0 = (uint32_t)(wm * 32 + (lid & 15)) * 128u;
    const uint32_t aoff1 = aoff0 + 16u * 128u;
    const uint32_t akx   = ((uint32_t)(lid >> 4)) << 4;
    const uint32_t boff0 = (uint32_t)(wn * 32 + ((lid >> 4) << 3) + (lid & 7)) * 128u;
    const uint32_t boff1 = boff0 + 16u * 128u;
    const uint32_t bkx   = ((uint32_t)((lid >> 3) & 1)) << 4;

    float acc[2][4][4];
#pragma unroll
    for (int mi = 0; mi < 2; mi++)
#pragma unroll
        for (int ni = 0; ni < 4; ni++)
#pragma unroll
            for (int r = 0; r < 4; r++) acc[mi][ni][r] = 0.f;

    float4 ra[8]; float4 rb[4];
    load_chunk(x, w, m0, 0, tid, ra, rb);

#pragma unroll 1
    for (int c = 0; c < NC; c++) {
        uint32_t sb = sbase + ((c & 1) ? STG : 0);
        uint32_t AH = sb + AH_O, AL = sb + AL_O, BH = sb + BH_O, BL = sb + BL_O;

#pragma unroll
        for (int j = 0; j < 8; j++) {
            int s = tid + j * 256;
            cvtst(ra[j], AH, AL, s >> 4, s & 15);
        }
#pragma unroll
        for (int j = 0; j < 4; j++) {
            int s = tid + j * 256;
            cvtst(rb[j], BH, BL, s >> 4, s & 15);
        }
        if (c + 1 < NC) load_chunk(x, w, m0, (c + 1) * KC, tid, ra, rb);
        __syncthreads();

#pragma unroll
        for (int ks = 0; ks < 4; ks++) {
            const uint32_t kb = (uint32_t)ks * 32u;
            const uint32_t ka = (kb + akx) ^ sxor;
            const uint32_t kbb = (kb + bkx) ^ sxor;
            uint32_t aH[2][4], aL[2][4], bH[2][4], bL[2][4];
            LDM4(aH[0], AH + aoff0 + ka);  LDM4(aH[1], AH + aoff1 + ka);
            LDM4(aL[0], AL + aoff0 + ka);  LDM4(aL[1], AL + aoff1 + ka);
            LDM4(bH[0], BH + boff0 + kbb); LDM4(bH[1], BH + boff1 + kbb);
            LDM4(bL[0], BL + boff0 + kbb); LDM4(bL[1], BL + boff1 + kbb);
#pragma unroll
            for (int mi = 0; mi < 2; mi++)
#pragma unroll
                for (int ni = 0; ni < 4; ni++) {
                    uint32_t* bh = &bH[ni >> 1][(ni & 1) * 2];
                    uint32_t* bl = &bL[ni >> 1][(ni & 1) * 2];
                    MMA(acc[mi][ni], aH[mi], bh[0], bh[1]);   // Ah*Bh
                    MMA(acc[mi][ni], aH[mi], bl[0], bl[1]);   // Ah*Bl
                    MMA(acc[mi][ni], aL[mi], bh[0], bh[1]);   // Al*Bh
                }
        }
    }
    __syncthreads();

    // ---- stage logits [128][65] into smem (overlays stage buffers) ----
    float* ls = (float*)(dsm_raw + (sbase - raw));
    {
        int g = lid >> 2, tg = lid & 3;
#pragma unroll
        for (int mi = 0; mi < 2; mi++)
#pragma unroll
            for (int ni = 0; ni < 4; ni++) {
                int r0 = wm * 32 + mi * 16 + g;
                int col = wn * 32 + ni * 8 + tg * 2;
                ls[r0 * 65 + col]           = acc[mi][ni][0];
                ls[r0 * 65 + col + 1]       = acc[mi][ni][1];
                ls[(r0 + 8) * 65 + col]     = acc[mi][ni][2];
                ls[(r0 + 8) * 65 + col + 1] = acc[mi][ni][3];
            }
    }
    __syncthreads();

    // ---- per-token epilogue: thread t < 128 owns token t ----
    float zs = 0.f;
    if (tid < MT) {
        float m1 = -1e30f, m2 = -1e30f, m3 = -1e30f;
        int i1 = 0, i2 = 0;
#pragma unroll
        for (int j = 0; j < E_NUM; j++) {
            float v = ls[tid * 65 + j];
            zs += v * v;
            if (v > m1)      { m3 = m2; m2 = m1; i2 = i1; m1 = v; i1 = j; }
            else if (v > m2) { m3 = m2; m2 = v; i2 = j; }
            else if (v > m3) { m3 = v; }
        }
        float s = 0.f;
#pragma unroll
        for (int j = 0; j < E_NUM; j++)
            s += expf(ls[tid * 65 + j] - m1);

        int tok = m0 + tid;
        out[tok * 2 + 0] = (float)i1;
        out[tok * 2 + 1] = (float)i2;
        out[2 * M_TOT + tok * 2 + 0] = 1.0f / s;
        out[2 * M_TOT + tok * 2 + 1] = expf(m2 - m1) / s;
        g_flags[tok] = ((m1 - m2 < GAP_TH) || (m2 - m3 < GAP_TH)) ? 1 : 0;
    }

    // ---- z partial reduction ----
#pragma unroll
    for (int o = 16; o > 0; o >>= 1)
        zs += __shfl_xor_sync(0xffffffffu, zs, o);
    if (lid == 0) zsh[wid] = zs;
    __syncthreads();
    if (tid == 0) {
        float s = 0.f;
#pragma unroll
        for (int i = 0; i < 8; i++) s += zsh[i];
        g_partials[blockIdx.x] = s;
    }
}

// Exact fp32 recompute for flagged (ambiguous-gap) tokens. ~100-300 tokens total.
__global__ __launch_bounds__(256) void router_fixup(
    const float* __restrict__ x, const float* __restrict__ w, float* __restrict__ out)
{
    __shared__ float red[E_NUM][5];
    __shared__ float lg[E_NUM];
    __shared__ int list[256];
    __shared__ int cnt;

    const int tid = threadIdx.x;
    if (tid == 0) cnt = 0;
    __syncthreads();

    int tok = blockIdx.x * 256 + tid;
    if (g_flags[tok]) { int p = atomicAdd(&cnt, 1); list[p] = tok; }
    __syncthreads();
    const int n = cnt;

    const int e = tid >> 2, q = tid & 3;
    for (int i = 0; i < n; i++) {
        int t = list[i];
        const float4* xp = (const float4*)(x + (size_t)t * H_DIM) + q * 256;
        const float4* wp = (const float4*)(w + (size_t)e * H_DIM) + q * 256;
        float s = 0.f;
#pragma unroll 4
        for (int k = 0; k < 256; k++) {
            float4 a = xp[k], b = wp[k];
            s += a.x * b.x; s += a.y * b.y; s += a.z * b.z; s += a.w * b.w;
        }
        red[e][q] = s;
        __syncthreads();
        if (tid < E_NUM)
            lg[tid] = (red[tid][0] + red[tid][1]) + (red[tid][2] + red[tid][3]);
        __syncthreads();
        if (tid == 0) {
            float m1 = -1e30f, m2 = -1e30f;
            int i1 = 0, i2 = 0;
            for (int j = 0; j < E_NUM; j++) {
                float v = lg[j];
                if (v > m1)      { m2 = m1; i2 = i1; m1 = v; i1 = j; }
                else if (v > m2) { m2 = v; i2 = j; }
            }
            float s2 = 0.f;
            for (int j = 0; j < E_NUM; j++) s2 += expf(lg[j] - m1);
            out[t * 2 + 0] = (float)i1;
            out[t * 2 + 1] = (float)i2;
            out[2 * M_TOT + t * 2 + 0] = 1.0f / s2;
            out[2 * M_TOT + t * 2 + 1] = expf(m2 - m1) / s2;
        }
        __syncthreads();
    }
}

__global__ __launch_bounds__(128) void router_finalize(float* __restrict__ out)
{
    __shared__ float sh[128];
    int tid = threadIdx.x;
    sh[tid] = g_partials[tid];
    __syncthreads();
#pragma unroll
    for (int s = 64; s > 0; s >>= 1) {
        if (tid < s) sh[tid] += sh[tid + s];
        __syncthreads();
    }
    if (tid == 0) {
        out[4 * M_TOT + 0] = 0.0f;
        out[4 * M_TOT + 1] = sh[0] / ((float)M_TOT * (float)E_NUM);
    }
}

extern "C" void kernel_launch(void* const* d_in, const int* in_sizes, int n_in,
                              void* d_out, int out_size)
{
    const float* x = (const float*)d_in[0];   // [4,4096,4096]
    const float* w = (const float*)d_in[1];   // [64,4096]
    float* out = (float*)d_out;

    cudaFuncSetAttribute(router_main, cudaFuncAttributeMaxDynamicSharedMemorySize, DSMB);
    router_main<<<NBLK, 256, DSMB>>>(x, w, out);
    router_fixup<<<M_TOT / 256, 256>>>(x, w, out);
    router_finalize<<<1, 128>>>(out);
}

// round 8
// speedup vs baseline: 5.1248x; 5.1248x over previous
#include <cuda_runtime.h>
#include <cuda_bf16.h>
#include <math.h>
#include <stdint.h>

// TopKRouter: x[4,4096,4096] fp32, gate_w[64,4096] fp32
// logits = x @ w^T [16384,64]; softmax; top-2; z_loss = mean(logits^2)
// out fp32: [0,32768) idx | [32768,65536) scores | [65536] aux=0 | [65537] z_loss
//
// sm_103 BASE target. GEMM via mma.sync bf16 hi/lo split (3 passes), with
// cvt/STS of chunk c+1 and LDG of chunk c+2 interleaved into the MMA stream
// of chunk c. Exact fp32 fixup (coalesced) for ambiguous-gap tokens.

#define M_TOT 16384
#define H_DIM 4096
#define E_NUM 64
#define MT    128
#define KC    64
#define NC    (H_DIM / KC)     // 64
#define NBLK  (M_TOT / MT)     // 128
#define GAP_TH 3e-4f

#define AH_O 0
#define AL_O 16384
#define BH_O 32768
#define BL_O 40960
#define STG  49152
#define DSMB (2 * STG + 128)   // 98432

__device__ float g_partials[NBLK];
__device__ unsigned char g_flags[M_TOT];

__device__ __forceinline__ uint32_t smem_u32(const void* p) {
    uint32_t a;
    asm("{ .reg .u64 t; cvta.to.shared.u64 t, %1; cvt.u32.u64 %0, t; }" : "=r"(a) : "l"(p));
    return a;
}

#define LDM4(r, a) \
    asm volatile("ldmatrix.sync.aligned.m8n8.x4.shared.b16 {%0,%1,%2,%3}, [%4];" \
        : "=r"((r)[0]), "=r"((r)[1]), "=r"((r)[2]), "=r"((r)[3]) : "r"(a))

#define MMA(c, a, b0, b1) \
    asm volatile("mma.sync.aligned.m16n8k16.row.col.f32.bf16.bf16.f32 " \
        "{%0,%1,%2,%3},{%4,%5,%6,%7},{%8,%9},{%0,%1,%2,%3};" \
        : "+f"((c)[0]), "+f"((c)[1]), "+f"((c)[2]), "+f"((c)[3]) \
        : "r"((a)[0]), "r"((a)[1]), "r"((a)[2]), "r"((a)[3]), "r"(b0), "r"(b1))

// split float4 into bf16 hi/lo quads, store 8B each (SW128-style swizzle)
__device__ __forceinline__ void cvtst(float4 v, uint32_t hi, uint32_t lo, int row, int q) {
    uint32_t off = (uint32_t)row * 128u + (((uint32_t)q * 8u) ^ (((uint32_t)row & 7u) << 4));
    uint32_t h01, h23, l01, l23;
    asm("cvt.rn.bf16x2.f32 %0, %1, %2;" : "=r"(h01) : "f"(v.y), "f"(v.x));
    asm("cvt.rn.bf16x2.f32 %0, %1, %2;" : "=r"(h23) : "f"(v.w), "f"(v.z));
    float hx = __uint_as_float(h01 << 16), hy = __uint_as_float(h01 & 0xffff0000u);
    float hz = __uint_as_float(h23 << 16), hw = __uint_as_float(h23 & 0xffff0000u);
    asm("cvt.rn.bf16x2.f32 %0, %1, %2;" : "=r"(l01) : "f"(v.y - hy), "f"(v.x - hx));
    asm("cvt.rn.bf16x2.f32 %0, %1, %2;" : "=r"(l23) : "f"(v.w - hw), "f"(v.z - hz));
    asm volatile("st.shared.v2.u32 [%0], {%1,%2};" :: "r"(hi + off), "r"(h01), "r"(h23) : "memory");
    asm volatile("st.shared.v2.u32 [%0], {%1,%2};" :: "r"(lo + off), "r"(l01), "r"(l23) : "memory");
}

extern __shared__ char dsm_raw[];

// one chunk iteration; DO_CVT: convert regs (chunk c+1) into write-buffer;
// DO_LDG: fetch chunk c+2 into regs.
template <bool DO_CVT, bool DO_LDG>
__device__ __forceinline__ void chunk_iter(
    int c, const float* __restrict__ x, const float* __restrict__ w, int m0, int tid,
    uint32_t sbase, float4 (&ra)[8], float4 (&rb4)[4],
    const uint32_t sxor, const uint32_t aoff0, const uint32_t aoff1, const uint32_t akx,
    const uint32_t boff0, const uint32_t boff1, const uint32_t bkx,
    float (&acc)[2][4][4])
{
    const uint32_t rbuf = sbase + ((c & 1) ? STG : 0);
    const uint32_t wbuf = sbase + ((c & 1) ? 0 : STG);
    const uint32_t AH = rbuf + AH_O, AL = rbuf + AL_O, BH = rbuf + BH_O, BL = rbuf + BL_O;
    const uint32_t AHw = wbuf + AH_O, ALw = wbuf + AL_O, BHw = wbuf + BH_O, BLw = wbuf + BL_O;
    const int k0n2 = (c + 2) * KC;

#pragma unroll
    for (int ks = 0; ks < 4; ks++) {
        const uint32_t kb = (uint32_t)ks * 32u;
        const uint32_t ka  = (kb + akx) ^ sxor;
        const uint32_t kbb = (kb + bkx) ^ sxor;
        uint32_t aH[2][4], aL[2][4], bH[2][4], bL[2][4];
        LDM4(aH[0], AH + aoff0 + ka);  LDM4(aH[1], AH + aoff1 + ka);
        LDM4(aL[0], AL + aoff0 + ka);  LDM4(aL[1], AL + aoff1 + ka);
        LDM4(bH[0], BH + boff0 + kbb); LDM4(bH[1], BH + boff1 + kbb);
        LDM4(bL[0], BL + boff0 + kbb); LDM4(bL[1], BL + boff1 + kbb);
#pragma unroll
        for (int mi = 0; mi < 2; mi++)
#pragma unroll
            for (int ni = 0; ni < 4; ni++) {
                uint32_t* bh = &bH[ni >> 1][(ni & 1) * 2];
                uint32_t* bl = &bL[ni >> 1][(ni & 1) * 2];
                MMA(acc[mi][ni], aH[mi], bh[0], bh[1]);   // Ah*Bh
                MMA(acc[mi][ni], aH[mi], bl[0], bl[1]);   // Ah*Bl
                MMA(acc[mi][ni], aL[mi], bh[0], bh[1]);   // Al*Bh
            }

        // splice convert of chunk c+1 (2 A quads + 1 B quad per ks)
        if (DO_CVT) {
            const int j0 = ks * 2;
            { int s = tid + j0 * 256;       cvtst(ra[j0],     AHw, ALw, s >> 4, s & 15); }
            { int s = tid + (j0 + 1) * 256; cvtst(ra[j0 + 1], AHw, ALw, s >> 4, s & 15); }
            { int s = tid + ks * 256;       cvtst(rb4[ks],    BHw, BLw, s >> 4, s & 15); }
        }
        // splice LDG of chunk c+2 into the just-freed registers
        if (DO_LDG) {
            const int j0 = ks * 2;
            { int s = tid + j0 * 256;       int r = s >> 4, q = s & 15;
              ra[j0]     = *(const float4*)&x[(size_t)(m0 + r) * H_DIM + k0n2 + q * 4]; }
            { int s = tid + (j0 + 1) * 256; int r = s >> 4, q = s & 15;
              ra[j0 + 1] = *(const float4*)&x[(size_t)(m0 + r) * H_DIM + k0n2 + q * 4]; }
            { int s = tid + ks * 256;       int r = s >> 4, q = s & 15;
              rb4[ks]    = *(const float4*)&w[(size_t)r * H_DIM + k0n2 + q * 4]; }
        }
    }
    __syncthreads();
}

__global__ __launch_bounds__(256, 1)
void router_main(const float* __restrict__ x, const float* __restrict__ w,
                 float* __restrict__ out)
{
    __shared__ float zsh[8];

    const int tid = threadIdx.x;
    const int wid = tid >> 5, lid = tid & 31;
    const int wm = wid & 3, wn = wid >> 2;
    const int m0 = blockIdx.x * MT;

    uint32_t raw   = smem_u32(dsm_raw);
    uint32_t sbase = (raw + 127u) & ~127u;

    const uint32_t sxor  = ((uint32_t)(lid & 7)) << 4;
    const uint32_t aoff0 = (uint32_t)(wm * 32 + (lid & 15)) * 128u;
    const uint32_t aoff1 = aoff0 + 16u * 128u;
    const uint32_t akx   = ((uint32_t)(lid >> 4)) << 4;
    const uint32_t boff0 = (uint32_t)(wn * 32 + ((lid >> 4) << 3) + (lid & 7)) * 128u;
    const uint32_t boff1 = boff0 + 16u * 128u;
    const uint32_t bkx   = ((uint32_t)((lid >> 3) & 1)) << 4;

    float acc[2][4][4];
#pragma unroll
    for (int mi = 0; mi < 2; mi++)
#pragma unroll
        for (int ni = 0; ni < 4; ni++)
#pragma unroll
            for (int r = 0; r < 4; r++) acc[mi][ni][r] = 0.f;

    float4 ra[8]; float4 rb4[4];

    // prologue: chunk 0 -> regs -> buf0; chunk 1 -> regs
#pragma unroll
    for (int j = 0; j < 8; j++) {
        int s = tid + j * 256, r = s >> 4, q = s & 15;
        ra[j] = *(const float4*)&x[(size_t)(m0 + r) * H_DIM + q * 4];
    }
#pragma unroll
    for (int j = 0; j < 4; j++) {
        int s = tid + j * 256, r = s >> 4, q = s & 15;
        rb4[j] = *(const float4*)&w[(size_t)r * H_DIM + q * 4];
    }
    {
        uint32_t AH = sbase + AH_O, AL = sbase + AL_O, BH = sbase + BH_O, BL = sbase + BL_O;
#pragma unroll
        for (int j = 0; j < 8; j++) { int s = tid + j * 256; cvtst(ra[j],  AH, AL, s >> 4, s & 15); }
#pragma unroll
        for (int j = 0; j < 4; j++) { int s = tid + j * 256; cvtst(rb4[j], BH, BL, s >> 4, s & 15); }
    }
    __syncthreads();
#pragma unroll
    for (int j = 0; j < 8; j++) {
        int s = tid + j * 256, r = s >> 4, q = s & 15;
        ra[j] = *(const float4*)&x[(size_t)(m0 + r) * H_DIM + KC + q * 4];
    }
#pragma unroll
    for (int j = 0; j < 4; j++) {
        int s = tid + j * 256, r = s >> 4, q = s & 15;
        rb4[j] = *(const float4*)&w[(size_t)r * H_DIM + KC + q * 4];
    }

#pragma unroll 1
    for (int c = 0; c < NC - 2; c++)
        chunk_iter<true, true>(c, x, w, m0, tid, sbase, ra, rb4,
                               sxor, aoff0, aoff1, akx, boff0, boff1, bkx, acc);
    chunk_iter<true,  false>(NC - 2, x, w, m0, tid, sbase, ra, rb4,
                             sxor, aoff0, aoff1, akx, boff0, boff1, bkx, acc);
    chunk_iter<false, false>(NC - 1, x, w, m0, tid, sbase, ra, rb4,
                             sxor, aoff0, aoff1, akx, boff0, boff1, bkx, acc);

    // ---- stage logits [128][65] into smem ----
    float* ls = (float*)(dsm_raw + (sbase - raw));
    {
        int g = lid >> 2, tg = lid & 3;
#pragma unroll
        for (int mi = 0; mi < 2; mi++)
#pragma unroll
            for (int ni = 0; ni < 4; ni++) {
                int r0 = wm * 32 + mi * 16 + g;
                int col = wn * 32 + ni * 8 + tg * 2;
                ls[r0 * 65 + col]           = acc[mi][ni][0];
                ls[r0 * 65 + col + 1]       = acc[mi][ni][1];
                ls[(r0 + 8) * 65 + col]     = acc[mi][ni][2];
                ls[(r0 + 8) * 65 + col + 1] = acc[mi][ni][3];
            }
    }
    __syncthreads();

    // ---- per-token epilogue ----
    float zs = 0.f;
    if (tid < MT) {
        float m1 = -1e30f, m2 = -1e30f, m3 = -1e30f;
        int i1 = 0, i2 = 0;
#pragma unroll
        for (int j = 0; j < E_NUM; j++) {
            float v = ls[tid * 65 + j];
            zs += v * v;
            if (v > m1)      { m3 = m2; m2 = m1; i2 = i1; m1 = v; i1 = j; }
            else if (v > m2) { m3 = m2; m2 = v; i2 = j; }
            else if (v > m3) { m3 = v; }
        }
        float s = 0.f;
#pragma unroll
        for (int j = 0; j < E_NUM; j++)
            s += expf(ls[tid * 65 + j] - m1);

        int tok = m0 + tid;
        out[tok * 2 + 0] = (float)i1;
        out[tok * 2 + 1] = (float)i2;
        out[2 * M_TOT + tok * 2 + 0] = 1.0f / s;
        out[2 * M_TOT + tok * 2 + 1] = expf(m2 - m1) / s;
        g_flags[tok] = ((m1 - m2 < GAP_TH) || (m2 - m3 < GAP_TH)) ? 1 : 0;
    }

#pragma unroll
    for (int o = 16; o > 0; o >>= 1)
        zs += __shfl_xor_sync(0xffffffffu, zs, o);
    if (lid == 0) zsh[wid] = zs;
    __syncthreads();
    if (tid == 0) {
        float s = 0.f;
#pragma unroll
        for (int i = 0; i < 8; i++) s += zsh[i];
        g_partials[blockIdx.x] = s;
    }
}

// Exact fp32 recompute for flagged tokens — COALESCED: warp w owns experts
// [w*8, w*8+8); lanes stride contiguously over k (x row stays L1-resident).
__global__ __launch_bounds__(256) void router_fixup(
    const float* __restrict__ x, const float* __restrict__ w, float* __restrict__ out)
{
    __shared__ float lg[E_NUM];
    __shared__ int list[256];
    __shared__ int cnt;

    const int tid = threadIdx.x;
    const int wid = tid >> 5, lid = tid & 31;
    if (tid == 0) cnt = 0;
    __syncthreads();

    int tok = blockIdx.x * 256 + tid;
    if (g_flags[tok]) { int p = atomicAdd(&cnt, 1); list[p] = tok; }
    __syncthreads();
    const int n = cnt;

    for (int i = 0; i < n; i++) {
        int t = list[i];
        const float4* xr = (const float4*)(x + (size_t)t * H_DIM);
#pragma unroll 1
        for (int e8 = 0; e8 < 8; e8++) {
            int e = wid * 8 + e8;
            const float4* wr = (const float4*)(w + (size_t)e * H_DIM);
            float s = 0.f;
#pragma unroll 4
            for (int j = lid; j < H_DIM / 4; j += 32) {
                float4 a = xr[j], b = wr[j];
                s += a.x * b.x + a.y * b.y + a.z * b.z + a.w * b.w;
            }
#pragma unroll
            for (int o = 16; o > 0; o >>= 1)
                s += __shfl_xor_sync(0xffffffffu, s, o);
            if (lid == 0) lg[e] = s;
        }
        __syncthreads();
        if (tid == 0) {
            float m1 = -1e30f, m2 = -1e30f;
            int i1 = 0, i2 = 0;
            for (int j = 0; j < E_NUM; j++) {
                float v = lg[j];
                if (v > m1)      { m2 = m1; i2 = i1; m1 = v; i1 = j; }
                else if (v > m2) { m2 = v; i2 = j; }
            }
            float s2 = 0.f;
            for (int j = 0; j < E_NUM; j++) s2 += expf(lg[j] - m1);
            out[t * 2 + 0] = (float)i1;
            out[t * 2 + 1] = (float)i2;
            out[2 * M_TOT + t * 2 + 0] = 1.0f / s2;
            out[2 * M_TOT + t * 2 + 1] = expf(m2 - m1) / s2;
        }
        __syncthreads();
    }
}

__global__ __launch_bounds__(128) void router_finalize(float* __restrict__ out)
{
    __shared__ float sh[128];
    int tid = threadIdx.x;
    sh[tid] = g_partials[tid];
    __syncthreads();
#pragma unroll
    for (int s = 64; s > 0; s >>= 1) {
        if (tid < s) sh[tid] += sh[tid + s];
        __syncthreads();
    }
    if (tid == 0) {
        out[4 * M_TOT + 0] = 0.0f;
        out[4 * M_TOT + 1] = sh[0] / ((float)M_TOT * (float)E_NUM);
    }
}

extern "C" void kernel_launch(void* const* d_in, const int* in_sizes, int n_in,
                              void* d_out, int out_size)
{
    const float* x = (const float*)d_in[0];   // [4,4096,4096]
    const float* w = (const float*)d_in[1];   // [64,4096]
    float* out = (float*)d_out;

    cudaFuncSetAttribute(router_main, cudaFuncAttributeMaxDynamicSharedMemorySize, DSMB);
    router_main<<<NBLK, 256, DSMB>>>(x, w, out);
    router_fixup<<<M_TOT / 256, 256>>>(x, w, out);
    router_finalize<<<1, 128>>>(out);
}

// round 9
// speedup vs baseline: 5.8554x; 1.1426x over previous
#include <cuda_runtime.h>
#include <cuda_bf16.h>
#include <math.h>
#include <stdint.h>

// TopKRouter: x[4,4096,4096] fp32, gate_w[64,4096] fp32
// logits = x @ w^T [16384,64]; softmax; top-2; z_loss = mean(logits^2)
// out fp32: [0,32768) idx | [32768,65536) scores | [65536] aux=0 | [65537] z_loss
//
// sm_103 BASE target. mma.sync bf16 hi/lo split (3 passes), 512 threads:
// 8 position-warps (32x32 tiles) x 2 k-groups (split-k), cvt/LDG spliced into
// the MMA stream. Exact fp32 fixup for ambiguous tokens inlined in-block.

#define M_TOT 16384
#define H_DIM 4096
#define E_NUM 64
#define MT    128
#define KC    64
#define NC    (H_DIM / KC)     // 64
#define NBLK  (M_TOT / MT)     // 128
#define NTHR  512
#define GAP_TH 3e-4f

#define AH_O 0
#define AL_O 16384
#define BH_O 32768
#define BL_O 40960
#define STG  49152
#define DSMB (2 * STG + 128)   // 98432

__device__ float g_partials[NBLK];

__device__ __forceinline__ uint32_t smem_u32(const void* p) {
    uint32_t a;
    asm("{ .reg .u64 t; cvta.to.shared.u64 t, %1; cvt.u32.u64 %0, t; }" : "=r"(a) : "l"(p));
    return a;
}

#define LDM4(r, a) \
    asm volatile("ldmatrix.sync.aligned.m8n8.x4.shared.b16 {%0,%1,%2,%3}, [%4];" \
        : "=r"((r)[0]), "=r"((r)[1]), "=r"((r)[2]), "=r"((r)[3]) : "r"(a))

#define MMA(c, a, b0, b1) \
    asm volatile("mma.sync.aligned.m16n8k16.row.col.f32.bf16.bf16.f32 " \
        "{%0,%1,%2,%3},{%4,%5,%6,%7},{%8,%9},{%0,%1,%2,%3};" \
        : "+f"((c)[0]), "+f"((c)[1]), "+f"((c)[2]), "+f"((c)[3]) \
        : "r"((a)[0]), "r"((a)[1]), "r"((a)[2]), "r"((a)[3]), "r"(b0), "r"(b1))

// split float4 into bf16 hi/lo quads, store 8B each (swizzled)
__device__ __forceinline__ void cvtst(float4 v, uint32_t hi, uint32_t lo, int row, int q) {
    uint32_t off = (uint32_t)row * 128u + (((uint32_t)q * 8u) ^ (((uint32_t)row & 7u) << 4));
    uint32_t h01, h23, l01, l23;
    asm("cvt.rn.bf16x2.f32 %0, %1, %2;" : "=r"(h01) : "f"(v.y), "f"(v.x));
    asm("cvt.rn.bf16x2.f32 %0, %1, %2;" : "=r"(h23) : "f"(v.w), "f"(v.z));
    float hx = __uint_as_float(h01 << 16), hy = __uint_as_float(h01 & 0xffff0000u);
    float hz = __uint_as_float(h23 << 16), hw = __uint_as_float(h23 & 0xffff0000u);
    asm("cvt.rn.bf16x2.f32 %0, %1, %2;" : "=r"(l01) : "f"(v.y - hy), "f"(v.x - hx));
    asm("cvt.rn.bf16x2.f32 %0, %1, %2;" : "=r"(l23) : "f"(v.w - hw), "f"(v.z - hz));
    asm volatile("st.shared.v2.u32 [%0], {%1,%2};" :: "r"(hi + off), "r"(h01), "r"(h23) : "memory");
    asm volatile("st.shared.v2.u32 [%0], {%1,%2};" :: "r"(lo + off), "r"(l01), "r"(l23) : "memory");
}

extern __shared__ char dsm_raw[];

// one chunk: MMAs on read-buffer; cvt regs(c+1)->write-buffer; LDG(c+2)->regs.
template <bool DO_CVT, bool DO_LDG>
__device__ __forceinline__ void chunk_iter(
    int c, const float* __restrict__ x, const float* __restrict__ w, int m0, int tid,
    int kgrp, uint32_t sbase, float4 (&ra)[4], float4 (&rb4)[2],
    const uint32_t sxor, const uint32_t aoff0, const uint32_t aoff1, const uint32_t akx,
    const uint32_t boff0, const uint32_t boff1, const uint32_t bkx,
    float (&acc)[2][4][4])
{
    const uint32_t rbuf = sbase + ((c & 1) ? STG : 0);
    const uint32_t wbuf = sbase + ((c & 1) ? 0 : STG);
    const uint32_t AH = rbuf + AH_O, AL = rbuf + AL_O, BH = rbuf + BH_O, BL = rbuf + BL_O;
    const uint32_t AHw = wbuf + AH_O, ALw = wbuf + AL_O, BHw = wbuf + BH_O, BLw = wbuf + BL_O;
    const int k0n2 = (c + 2) * KC;

#pragma unroll
    for (int ks = 0; ks < 2; ks++) {
        const uint32_t kb = (uint32_t)(kgrp * 2 + ks) * 32u;
        const uint32_t ka  = (kb + akx) ^ sxor;
        const uint32_t kbb = (kb + bkx) ^ sxor;
        uint32_t aH[2][4], aL[2][4], bH[2][4], bL[2][4];
        LDM4(aH[0], AH + aoff0 + ka);  LDM4(aH[1], AH + aoff1 + ka);
        LDM4(aL[0], AL + aoff0 + ka);  LDM4(aL[1], AL + aoff1 + ka);
        LDM4(bH[0], BH + boff0 + kbb); LDM4(bH[1], BH + boff1 + kbb);
        LDM4(bL[0], BL + boff0 + kbb); LDM4(bL[1], BL + boff1 + kbb);

        // pass-outer ordering: each acc re-issued every 8 MMAs (no 3-chains)
#pragma unroll
        for (int mi = 0; mi < 2; mi++)
#pragma unroll
            for (int ni = 0; ni < 4; ni++) {
                uint32_t* bh = &bH[ni >> 1][(ni & 1) * 2];
                MMA(acc[mi][ni], aH[mi], bh[0], bh[1]);       // Ah*Bh
            }
#pragma unroll
        for (int mi = 0; mi < 2; mi++)
#pragma unroll
            for (int ni = 0; ni < 4; ni++) {
                uint32_t* bl = &bL[ni >> 1][(ni & 1) * 2];
                MMA(acc[mi][ni], aH[mi], bl[0], bl[1]);       // Ah*Bl
            }
#pragma unroll
        for (int mi = 0; mi < 2; mi++)
#pragma unroll
            for (int ni = 0; ni < 4; ni++) {
                uint32_t* bh = &bH[ni >> 1][(ni & 1) * 2];
                MMA(acc[mi][ni], aL[mi], bh[0], bh[1]);       // Al*Bh
            }

        if (DO_CVT) {
            const int j0 = ks * 2;
            { int s = tid + j0 * NTHR;       cvtst(ra[j0],     AHw, ALw, s >> 4, s & 15); }
            { int s = tid + (j0 + 1) * NTHR; cvtst(ra[j0 + 1], AHw, ALw, s >> 4, s & 15); }
            { int s = tid + ks * NTHR;       cvtst(rb4[ks],    BHw, BLw, s >> 4, s & 15); }
        }
        if (DO_LDG) {
            const int j0 = ks * 2;
            { int s = tid + j0 * NTHR;       int r = s >> 4, q = s & 15;
              ra[j0]     = *(const float4*)&x[(size_t)(m0 + r) * H_DIM + k0n2 + q * 4]; }
            { int s = tid + (j0 + 1) * NTHR; int r = s >> 4, q = s & 15;
              ra[j0 + 1] = *(const float4*)&x[(size_t)(m0 + r) * H_DIM + k0n2 + q * 4]; }
            { int s = tid + ks * NTHR;       int r = s >> 4, q = s & 15;
              rb4[ks]    = *(const float4*)&w[(size_t)r * H_DIM + k0n2 + q * 4]; }
        }
    }
    __syncthreads();
}

__global__ __launch_bounds__(NTHR, 1)
void router_main(const float* __restrict__ x, const float* __restrict__ w,
                 float* __restrict__ out)
{
    __shared__ float zsh[4];
    __shared__ float lg[E_NUM];
    __shared__ int flist[32];
    __shared__ int fcnt;

    const int tid = threadIdx.x;
    const int wid = tid >> 5, lid = tid & 31;
    const int kgrp = wid >> 3;           // 0/1: k-slices {0,1} vs {2,3}
    const int pw   = wid & 7;            // position warp
    const int wm = pw & 3, wn = pw >> 2; // rows wm*32, experts wn*32
    const int m0 = blockIdx.x * MT;

    uint32_t raw   = smem_u32(dsm_raw);
    uint32_t sbase = (raw + 127u) & ~127u;

    const uint32_t sxor  = ((uint32_t)(lid & 7)) << 4;
    const uint32_t aoff0 = (uint32_t)(wm * 32 + (lid & 15)) * 128u;
    const uint32_t aoff1 = aoff0 + 16u * 128u;
    const uint32_t akx   = ((uint32_t)(lid >> 4)) << 4;
    const uint32_t boff0 = (uint32_t)(wn * 32 + ((lid >> 4) << 3) + (lid & 7)) * 128u;
    const uint32_t boff1 = boff0 + 16u * 128u;
    const uint32_t bkx   = ((uint32_t)((lid >> 3) & 1)) << 4;

    float acc[2][4][4];
#pragma unroll
    for (int mi = 0; mi < 2; mi++)
#pragma unroll
        for (int ni = 0; ni < 4; ni++)
#pragma unroll
            for (int r = 0; r < 4; r++) acc[mi][ni][r] = 0.f;

    float4 ra[4]; float4 rb4[2];

    // prologue: chunk 0 -> regs -> buf0; chunk 1 -> regs
#pragma unroll
    for (int j = 0; j < 4; j++) {
        int s = tid + j * NTHR, r = s >> 4, q = s & 15;
        ra[j] = *(const float4*)&x[(size_t)(m0 + r) * H_DIM + q * 4];
    }
#pragma unroll
    for (int j = 0; j < 2; j++) {
        int s = tid + j * NTHR, r = s >> 4, q = s & 15;
        rb4[j] = *(const float4*)&w[(size_t)r * H_DIM + q * 4];
    }
    {
        uint32_t AH = sbase + AH_O, AL = sbase + AL_O, BH = sbase + BH_O, BL = sbase + BL_O;
#pragma unroll
        for (int j = 0; j < 4; j++) { int s = tid + j * NTHR; cvtst(ra[j],  AH, AL, s >> 4, s & 15); }
#pragma unroll
        for (int j = 0; j < 2; j++) { int s = tid + j * NTHR; cvtst(rb4[j], BH, BL, s >> 4, s & 15); }
    }
    __syncthreads();
#pragma unroll
    for (int j = 0; j < 4; j++) {
        int s = tid + j * NTHR, r = s >> 4, q = s & 15;
        ra[j] = *(const float4*)&x[(size_t)(m0 + r) * H_DIM + KC + q * 4];
    }
#pragma unroll
    for (int j = 0; j < 2; j++) {
        int s = tid + j * NTHR, r = s >> 4, q = s & 15;
        rb4[j] = *(const float4*)&w[(size_t)r * H_DIM + KC + q * 4];
    }

#pragma unroll 1
    for (int c = 0; c < NC - 2; c++)
        chunk_iter<true, true>(c, x, w, m0, tid, kgrp, sbase, ra, rb4,
                               sxor, aoff0, aoff1, akx, boff0, boff1, bkx, acc);
    chunk_iter<true,  false>(NC - 2, x, w, m0, tid, kgrp, sbase, ra, rb4,
                             sxor, aoff0, aoff1, akx, boff0, boff1, bkx, acc);
    chunk_iter<false, false>(NC - 1, x, w, m0, tid, kgrp, sbase, ra, rb4,
                             sxor, aoff0, aoff1, akx, boff0, boff1, bkx, acc);

    // ---- merge split-k halves + stage logits [128][65] into smem ----
    if (tid == 0) fcnt = 0;
    float* ls = (float*)(dsm_raw + (sbase - raw));
    {
        int g = lid >> 2, tg = lid & 3;
        if (kgrp == 0) {
#pragma unroll
            for (int mi = 0; mi < 2; mi++)
#pragma unroll
                for (int ni = 0; ni < 4; ni++) {
                    int r0 = wm * 32 + mi * 16 + g;
                    int col = wn * 32 + ni * 8 + tg * 2;
                    ls[r0 * 65 + col]           = acc[mi][ni][0];
                    ls[r0 * 65 + col + 1]       = acc[mi][ni][1];
                    ls[(r0 + 8) * 65 + col]     = acc[mi][ni][2];
                    ls[(r0 + 8) * 65 + col + 1] = acc[mi][ni][3];
                }
        }
        __syncthreads();
        if (kgrp == 1) {
#pragma unroll
            for (int mi = 0; mi < 2; mi++)
#pragma unroll
                for (int ni = 0; ni < 4; ni++) {
                    int r0 = wm * 32 + mi * 16 + g;
                    int col = wn * 32 + ni * 8 + tg * 2;
                    ls[r0 * 65 + col]           += acc[mi][ni][0];
                    ls[r0 * 65 + col + 1]       += acc[mi][ni][1];
                    ls[(r0 + 8) * 65 + col]     += acc[mi][ni][2];
                    ls[(r0 + 8) * 65 + col + 1] += acc[mi][ni][3];
                }
        }
        __syncthreads();
    }

    // ---- per-token epilogue (threads 0..127 own one token each) ----
    float zs = 0.f;
    if (tid < MT) {
        float m1 = -1e30f, m2 = -1e30f, m3 = -1e30f;
        int i1 = 0, i2 = 0;
#pragma unroll
        for (int j = 0; j < E_NUM; j++) {
            float v = ls[tid * 65 + j];
            zs += v * v;
            if (v > m1)      { m3 = m2; m2 = m1; i2 = i1; m1 = v; i1 = j; }
            else if (v > m2) { m3 = m2; m2 = v; i2 = j; }
            else if (v > m3) { m3 = v; }
        }
        float s = 0.f;
#pragma unroll
        for (int j = 0; j < E_NUM; j++)
            s += expf(ls[tid * 65 + j] - m1);

        int tok = m0 + tid;
        out[tok * 2 + 0] = (float)i1;
        out[tok * 2 + 1] = (float)i2;
        out[2 * M_TOT + tok * 2 + 0] = 1.0f / s;
        out[2 * M_TOT + tok * 2 + 1] = expf(m2 - m1) / s;
        if ((m1 - m2 < GAP_TH) || (m2 - m3 < GAP_TH)) {
            int p = atomicAdd(&fcnt, 1);
            if (p < 32) flist[p] = tid;
        }
    }

    // ---- z partial ----
    if (wid < 4) {
#pragma unroll
        for (int o = 16; o > 0; o >>= 1)
            zs += __shfl_xor_sync(0xffffffffu, zs, o);
        if (lid == 0) zsh[wid] = zs;
    }
    __syncthreads();
    if (tid == 0)
        g_partials[blockIdx.x] = zsh[0] + zsh[1] + zsh[2] + zsh[3];

    // ---- inline exact fp32 fixup for ambiguous tokens (rare: ~0.3/block) ----
    int nfix = fcnt < 32 ? fcnt : 32;
    for (int i = 0; i < nfix; i++) {
        int t = flist[i];
        int tok = m0 + t;
        const float4* xr = (const float4*)(x + (size_t)tok * H_DIM);
#pragma unroll 1
        for (int e4 = 0; e4 < 4; e4++) {
            int e = wid * 4 + e4;
            const float4* wr = (const float4*)(w + (size_t)e * H_DIM);
            float s = 0.f;
#pragma unroll 4
            for (int j = lid; j < H_DIM / 4; j += 32) {
                float4 a = xr[j], b = wr[j];
                s += a.x * b.x + a.y * b.y + a.z * b.z + a.w * b.w;
            }
#pragma unroll
            for (int o = 16; o > 0; o >>= 1)
                s += __shfl_xor_sync(0xffffffffu, s, o);
            if (lid == 0) lg[e] = s;
        }
        __syncthreads();
        if (tid == 0) {
            float m1 = -1e30f, m2 = -1e30f;
            int i1 = 0, i2 = 0;
            for (int j = 0; j < E_NUM; j++) {
                float v = lg[j];
                if (v > m1)      { m2 = m1; i2 = i1; m1 = v; i1 = j; }
                else if (v > m2) { m2 = v; i2 = j; }
            }
            float s2 = 0.f;
            for (int j = 0; j < E_NUM; j++) s2 += expf(lg[j] - m1);
            out[tok * 2 + 0] = (float)i1;
            out[tok * 2 + 1] = (float)i2;
            out[2 * M_TOT + tok * 2 + 0] = 1.0f / s2;
            out[2 * M_TOT + tok * 2 + 1] = expf(m2 - m1) / s2;
        }
        __syncthreads();
    }
}

__global__ __launch_bounds__(128) void router_finalize(float* __restrict__ out)
{
    __shared__ float sh[128];
    int tid = threadIdx.x;
    sh[tid] = g_partials[tid];
    __syncthreads();
#pragma unroll
    for (int s = 64; s > 0; s >>= 1) {
        if (tid < s) sh[tid] += sh[tid + s];
        __syncthreads();
    }
    if (tid == 0) {
        out[4 * M_TOT + 0] = 0.0f;
        out[4 * M_TOT + 1] = sh[0] / ((float)M_TOT * (float)E_NUM);
    }
}

extern "C" void kernel_launch(void* const* d_in, const int* in_sizes, int n_in,
                              void* d_out, int out_size)
{
    const float* x = (const float*)d_in[0];   // [4,4096,4096]
    const float* w = (const float*)d_in[1];   // [64,4096]
    float* out = (float*)d_out;

    cudaFuncSetAttribute(router_main, cudaFuncAttributeMaxDynamicSharedMemorySize, DSMB);
    router_main<<<NBLK, NTHR, DSMB>>>(x, w, out);
    router_finalize<<<1, 128>>>(out);
}